// round 9
// baseline (speedup 1.0000x reference)
#include <cuda_runtime.h>
#include <cstdint>

// ---------------------------------------------------------------------------
// FocalLoss (RetinaNet) — single-kernel block-specialized producer/consumer.
// B=8, A=65536, C=80, M=32.
//
// 592 blocks x 320 threads, all resident in ONE wave (__launch_bounds__(320,4)).
//   blocks [0,148)   : ASSIGNERS — one per SM. For each owned tile (512
//                      anchors) compute division-free IoU argmax
//                      (iou_m > iou_b <=> inter_m*S_b > inter_b*S_m,
//                       S = area_a + area_m; thresholds 3*inter>=S (0.5),
//                       3.5*inter>=S (0.4)), write per-anchor weight
//                      w in {0 (ignore), NEG_W (valid)} to g_w, accumulate
//                      smooth-L1 reg loss + positive count + the per-positive
//                      classification fix-up, then RELEASE the tile flag.
//   blocks [148,592) : STREAMERS — pull tiles from an atomic queue (perfect
//                      balance), ACQUIRE the flag, then stream the tile's
//                      [512,80] classifications as ulonglong2 with packed
//                      f32x2 math:  clssum += w * v^2 * max(lg2(1-v), LCL).
// ALPHA=0.5 makes both focal branches share the 0.5 factor, so the stream
// needs only the negative formula; positives are fixed up by the assigner.
// Last block (global ticket) finalizes out[2] and resets all scratch for the
// next CUDA-graph replay. Assigners never wait on streamers => deadlock-free.
// ---------------------------------------------------------------------------

#define MAX_B     8
#define MAX_M     64
#define MAX_BA    (8 * 65536)
#define MAX_TILES 2048
#define ABLK      512
#define NTHR      320
#define NWARP     (NTHR / 32)
#define NASSIGN   148
#define NSTREAM   444

__device__ double g_cls_sum[MAX_B];
__device__ double g_reg_sum[MAX_B];
__device__ int    g_pos_cnt[MAX_B];
__device__ int    g_done;
__device__ int    g_tile_ctr;
__device__ int    g_flag[MAX_TILES];
__device__ float  g_w[MAX_BA];

__device__ __forceinline__ float lg2f(float x) {
    float r;
    asm("lg2.approx.f32 %0, %1;" : "=f"(r) : "f"(x));
    return r;
}

typedef unsigned long long ull;

__device__ __forceinline__ ull pack2(float lo, float hi) {
    ull r; asm("mov.b64 %0, {%1, %2};" : "=l"(r) : "f"(lo), "f"(hi)); return r;
}
__device__ __forceinline__ void unpack2(ull v, float& lo, float& hi) {
    asm("mov.b64 {%0, %1}, %2;" : "=f"(lo), "=f"(hi) : "l"(v));
}
__device__ __forceinline__ ull fma2(ull a, ull b, ull c) {
    ull r; asm("fma.rn.f32x2 %0, %1, %2, %3;" : "=l"(r) : "l"(a), "l"(b), "l"(c)); return r;
}
__device__ __forceinline__ ull mul2(ull a, ull b) {
    ull r; asm("mul.rn.f32x2 %0, %1, %2;" : "=l"(r) : "l"(a), "l"(b)); return r;
}

#define LCL   (-13.28771237954945f)        /* lg2(1e-4) */
#define NEG_W (-0.34657359027997264f)      /* -0.5*ln(2) */

// acc += wgt2 * v^2 * max(lg2(1-v), LCL) for 4 elements (packed pairs)
__device__ __forceinline__ void neg4_acc(ull w01, ull w23, ull wgt2,
                                         ull& acc0, ull& acc1,
                                         ull NEG1, ull ONE2) {
    ull q01 = fma2(w01, NEG1, ONE2);     // 1 - v
    ull q23 = fma2(w23, NEG1, ONE2);
    float q0, q1, q2, q3;
    unpack2(q01, q0, q1); unpack2(q23, q2, q3);
    float l0 = fmaxf(lg2f(q0), LCL), l1 = fmaxf(lg2f(q1), LCL);
    float l2 = fmaxf(lg2f(q2), LCL), l3 = fmaxf(lg2f(q3), LCL);
    ull L01 = pack2(l0, l1), L23 = pack2(l2, l3);
    ull t01 = mul2(w01, w01), t23 = mul2(w23, w23);
    acc0 = fma2(mul2(t01, L01), wgt2, acc0);
    acc1 = fma2(mul2(t23, L23), wgt2, acc1);
}

__global__ void __launch_bounds__(NTHR, 4)
focal_ws_kernel(const float* __restrict__ cls,          // [B,A,C]
                const float* __restrict__ regressions,  // [B,A,4]
                const float* __restrict__ anchors,      // [A,4]
                const float* __restrict__ annotations,  // [B,M,5]
                float* __restrict__ out,
                int A, int C, int M, int B,
                int bx, int nTiles, int total_blocks)
{
    const int tid  = threadIdx.x;
    const int lane = tid & 31;
    const int warp = tid >> 5;

    __shared__ float4 s_box[MAX_M];
    __shared__ float  s_area[MAX_M];
    __shared__ float  s_lab[MAX_M];
    __shared__ float  s_w[ABLK];
    __shared__ float  sw_c[NWARP], sw_r[NWARP];
    __shared__ int    sw_i[NWARP];
    __shared__ int    s_t;
    __shared__ int    s_last;

    if (blockIdx.x < NASSIGN) {
        // ================= ASSIGNER =================
        for (int t = blockIdx.x; t < nTiles; t += NASSIGN) {
            const int b  = t / bx;
            const int a0 = (t - b * bx) * ABLK;
            const int nA = min(ABLK, A - a0);

            __syncthreads();               // protect smem reuse across tiles
            if (tid < M) {
                const float* an = annotations + (size_t)b * M * 5 + tid * 5;
                float x1 = an[0], y1 = an[1], x2 = an[2], y2 = an[3];
                s_box[tid]  = make_float4(x1, y1, x2, y2);
                s_area[tid] = (x2 - x1) * (y2 - y1);
                s_lab[tid]  = an[4];
            }
            __syncthreads();

            float fixsum = 0.0f, regsum = 0.0f;
            int   poscnt = 0;

            for (int la = tid; la < nA; la += NTHR) {
                const int a = a0 + la;
                float4 an = reinterpret_cast<const float4*>(anchors)[a];
                float aw = an.z - an.x;
                float ah = an.w - an.y;
                float area_a = aw * ah;

                float bin, bS;
                int   bi = 0;
                {
                    float4 bxo = s_box[0];
                    float iw = fmaxf(fminf(an.z, bxo.z) - fmaxf(an.x, bxo.x), 0.0f);
                    float ih = fmaxf(fminf(an.w, bxo.w) - fmaxf(an.y, bxo.y), 0.0f);
                    bin = iw * ih;
                    bS  = area_a + s_area[0];
                }
                #pragma unroll 8
                for (int m = 1; m < M; m++) {
                    float4 bxo = s_box[m];
                    float iw = fmaxf(fminf(an.z, bxo.z) - fmaxf(an.x, bxo.x), 0.0f);
                    float ih = fmaxf(fminf(an.w, bxo.w) - fmaxf(an.y, bxo.y), 0.0f);
                    float inter = iw * ih;
                    float S     = area_a + s_area[m];
                    // iou_m > iou_best <=> inter*bS > bin*S (cross terms cancel)
                    if (inter * bS > bin * S) { bi = m; bin = inter; bS = S; }
                }

                // iou = bin/(bS-bin): >=0.5 <=> 3*bin>=bS ; >=0.4 <=> 3.5*bin>=bS
                bool pos = (3.0f * bin >= bS);
                bool ign = (!pos) && (3.5f * bin >= bS);
                g_w[(size_t)b * A + a] = ign ? 0.0f : NEG_W;

                if (pos) {
                    poscnt++;
                    float4 gb = s_box[bi];
                    float gw = gb.z - gb.x, gh = gb.w - gb.y;
                    float gcx = gb.x + 0.5f * gw, gcy = gb.y + 0.5f * gh;
                    gw = fmaxf(gw, 1.0f);
                    gh = fmaxf(gh, 1.0f);
                    float acx = an.x + 0.5f * aw, acy = an.y + 0.5f * ah;
                    float t0 = __fdividef(gcx - acx, aw) * 10.0f;
                    float t1 = __fdividef(gcy - acy, ah) * 10.0f;
                    float t2 = __logf(__fdividef(gw, aw)) * 5.0f;
                    float t3 = __logf(__fdividef(gh, ah)) * 5.0f;

                    float4 rg = reinterpret_cast<const float4*>(regressions)[(size_t)b * A + a];
                    const float th = 1.0f / 9.0f;
                    const float c2 = 0.5f / 9.0f;
                    float d;
                    d = fabsf(t0 - rg.x); regsum += (d <= th) ? 4.5f * d * d : d - c2;
                    d = fabsf(t1 - rg.y); regsum += (d <= th) ? 4.5f * d * d : d - c2;
                    d = fabsf(t2 - rg.z); regsum += (d <= th) ? 4.5f * d * d : d - c2;
                    d = fabsf(t3 - rg.w); regsum += (d <= th) ? 4.5f * d * d : d - c2;

                    // classification fix-up for the true class
                    int label = (int)s_lab[bi];
                    float v = cls[((size_t)b * A + a) * C + label];
                    fixsum -= NEG_W * (v * v * fmaxf(lg2f(1.0f - v), LCL));
                    float pp = fminf(fmaxf(v, 1e-4f), 1.0f - 1e-4f);
                    float qq = 1.0f - pp;
                    fixsum += 0.5f * qq * qq * (-__logf(pp));
                }
            }

            __threadfence();   // w stores visible before flag release

            // per-tile block reduce (the syncthreads also orders the fences
            // of all threads before thread 0's flag release)
            #pragma unroll
            for (int off = 16; off > 0; off >>= 1) {
                fixsum += __shfl_down_sync(0xFFFFFFFFu, fixsum, off);
                regsum += __shfl_down_sync(0xFFFFFFFFu, regsum, off);
                poscnt += __shfl_down_sync(0xFFFFFFFFu, poscnt, off);
            }
            if (lane == 0) { sw_c[warp] = fixsum; sw_r[warp] = regsum; sw_i[warp] = poscnt; }
            __syncthreads();
            if (warp == 0) {
                float cs = (lane < NWARP) ? sw_c[lane] : 0.0f;
                float rs = (lane < NWARP) ? sw_r[lane] : 0.0f;
                int   pc = (lane < NWARP) ? sw_i[lane] : 0;
                #pragma unroll
                for (int off = 8; off > 0; off >>= 1) {
                    cs += __shfl_down_sync(0xFFFFFFFFu, cs, off);
                    rs += __shfl_down_sync(0xFFFFFFFFu, rs, off);
                    pc += __shfl_down_sync(0xFFFFFFFFu, pc, off);
                }
                if (lane == 0) {
                    if (cs != 0.0f) atomicAdd(&g_cls_sum[b], (double)cs);
                    if (rs != 0.0f) atomicAdd(&g_reg_sum[b], (double)rs);
                    if (pc != 0)    atomicAdd(&g_pos_cnt[b], pc);
                    atomicExch(&g_flag[t], 1);       // release tile
                }
            }
        }
    } else {
        // ================= STREAMER =================
        const ull NEG1 = pack2(-1.0f, -1.0f);
        const ull ONE2 = pack2(1.0f, 1.0f);

        while (true) {
            if (tid == 0) s_t = atomicAdd(&g_tile_ctr, 1);
            __syncthreads();
            const int t = s_t;
            if (t >= nTiles) break;
            const int b  = t / bx;
            const int a0 = (t - b * bx) * ABLK;
            const int nA = min(ABLK, A - a0);

            if (tid == 0) {
                while (atomicAdd(&g_flag[t], 0) == 0) __nanosleep(64);
            }
            __syncthreads();
            __threadfence();                         // acquire

            for (int i = tid; i < nA; i += NTHR)
                s_w[i] = g_w[(size_t)b * A + a0 + i];
            __syncthreads();

            float clssum = 0.0f;
            if (C == 80 && nA == ABLK) {
                const ulonglong2* base = reinterpret_cast<const ulonglong2*>(
                    cls + ((size_t)b * A + a0) * 80);
                ull acc0 = pack2(0.0f, 0.0f), acc1 = pack2(0.0f, 0.0f);
                ull acc2 = pack2(0.0f, 0.0f), acc3 = pack2(0.0f, 0.0f);
                int idx = tid;
                int la  = tid / 20;
                #pragma unroll
                for (int k = 0; k < 8; k++) {
                    ulonglong2 v0 = base[idx];
                    ulonglong2 v1 = base[idx + NTHR];
                    ulonglong2 v2 = base[idx + 2 * NTHR];
                    ulonglong2 v3 = base[idx + 3 * NTHR];
                    float w0 = s_w[la], w1 = s_w[la + 16];
                    float w2 = s_w[la + 32], w3 = s_w[la + 48];
                    neg4_acc(v0.x, v0.y, pack2(w0, w0), acc0, acc1, NEG1, ONE2);
                    neg4_acc(v1.x, v1.y, pack2(w1, w1), acc2, acc3, NEG1, ONE2);
                    neg4_acc(v2.x, v2.y, pack2(w2, w2), acc0, acc1, NEG1, ONE2);
                    neg4_acc(v3.x, v3.y, pack2(w3, w3), acc2, acc3, NEG1, ONE2);
                    idx += 4 * NTHR;
                    la  += 64;
                }
                float s0, s1, s2, s3, s4, s5, s6, s7;
                unpack2(acc0, s0, s1); unpack2(acc1, s2, s3);
                unpack2(acc2, s4, s5); unpack2(acc3, s6, s7);
                clssum = ((s0 + s1) + (s2 + s3)) + ((s4 + s5) + (s6 + s7));
            } else {
                const ulonglong2* base = reinterpret_cast<const ulonglong2*>(
                    cls + ((size_t)b * A + a0) * C);
                const int n4 = (nA * C) >> 2;
                ull acc0 = pack2(0.0f, 0.0f), acc1 = pack2(0.0f, 0.0f);
                for (int idx = tid; idx < n4; idx += NTHR) {
                    int aa = (idx << 2) / C;
                    float w = s_w[aa];
                    ulonglong2 v = base[idx];
                    neg4_acc(v.x, v.y, pack2(w, w), acc0, acc1, NEG1, ONE2);
                }
                float s0, s1, s2, s3;
                unpack2(acc0, s0, s1); unpack2(acc1, s2, s3);
                clssum = (s0 + s1) + (s2 + s3);
            }

            // per-tile block reduce + single double atomic
            #pragma unroll
            for (int off = 16; off > 0; off >>= 1)
                clssum += __shfl_down_sync(0xFFFFFFFFu, clssum, off);
            if (lane == 0) sw_c[warp] = clssum;
            __syncthreads();
            if (warp == 0) {
                float cs = (lane < NWARP) ? sw_c[lane] : 0.0f;
                #pragma unroll
                for (int off = 8; off > 0; off >>= 1)
                    cs += __shfl_down_sync(0xFFFFFFFFu, cs, off);
                if (lane == 0) atomicAdd(&g_cls_sum[b], (double)cs);
            }
            __syncthreads();   // before smem reuse next tile
        }
    }

    // ================= ticket + finalize (any role) =================
    if (tid == 0) {
        __threadfence();
        int prev = atomicAdd(&g_done, 1);
        s_last = (prev == total_blocks - 1) ? 1 : 0;
    }
    __syncthreads();

    if (s_last) {
        __threadfence();
        if (warp == 0) {
            double cm = 0.0, rm = 0.0;
            if (lane < B) {
                double cv = *((volatile double*)&g_cls_sum[lane]);
                double rv = *((volatile double*)&g_reg_sum[lane]);
                int    pv = *((volatile int*)&g_pos_cnt[lane]);
                double np = (double)pv;
                cm = cv / fmax(np, 1.0);
                rm = (pv > 0) ? rv / fmax(np * 4.0, 1.0) : 0.0;
            }
            #pragma unroll
            for (int off = 16; off > 0; off >>= 1) {
                cm += __shfl_down_sync(0xFFFFFFFFu, cm, off);
                rm += __shfl_down_sync(0xFFFFFFFFu, rm, off);
            }
            if (lane == 0) {
                out[0] = (float)(cm / (double)B);
                out[1] = (float)(rm / (double)B);
            }
            if (lane < B) {
                g_cls_sum[lane] = 0.0;
                g_reg_sum[lane] = 0.0;
                g_pos_cnt[lane] = 0;
            }
        }
        // reset tile flags + counters for the next graph replay
        for (int i = tid; i < nTiles; i += NTHR) g_flag[i] = 0;
        if (tid == 0) { g_tile_ctr = 0; g_done = 0; }
    }
}

// ---------------------------------------------------------------------------
extern "C" void kernel_launch(void* const* d_in, const int* in_sizes, int n_in,
                              void* d_out, int out_size)
{
    const float* classifications = (const float*)d_in[0];  // [B,A,C]
    const float* regressions     = (const float*)d_in[1];  // [B,A,4]
    const float* anchors         = (const float*)d_in[2];  // [1,A,4]
    const float* annotations     = (const float*)d_in[3];  // [B,M,5]
    float* out = (float*)d_out;

    const int A = in_sizes[2] / 4;
    const int B = in_sizes[1] / (4 * A);
    const int C = in_sizes[0] / (B * A);
    const int M = in_sizes[3] / (5 * B);

    const int bx     = (A + ABLK - 1) / ABLK;
    const int nTiles = bx * B;
    const int grid   = NASSIGN + NSTREAM;   // 592 blocks, single resident wave

    focal_ws_kernel<<<grid, NTHR>>>(classifications, regressions, anchors,
                                    annotations, out, A, C, M, B,
                                    bx, nTiles, grid);
    (void)n_in; (void)out_size;
}

// round 16
// speedup vs baseline: 1.4152x; 1.4152x over previous
#include <cuda_runtime.h>
#include <cstdint>

// ---------------------------------------------------------------------------
// FocalLoss (RetinaNet) — persistent fused kernel, dynamic tile queue.
// B=8, A=65536, C=80, M=32.
// Each tile = 512 anchors of one image. A block pulls a tile from an atomic
// queue, runs phase A (assignment) then phase B (classification stream):
//   Phase A: division-free IoU argmax with the S-cancellation
//            (iou_m > iou_b <=> inter_m*S_b > inter_b*S_m, S=area_a+area_m;
//             thresholds 3*inter>=S (iou 0.5), 3.5*inter>=S (iou 0.4)),
//            smooth-L1 reg loss, positive count, per-positive cls fix-up.
//   Phase B: ALPHA=0.5 => only the negative focal formula is needed:
//            clssum += w * v^2 * max(lg2(1-v), lg2(1e-4)),  w in {0, -0.5ln2}.
//            8 front-batched __ldcs float4 loads per step (MLP=8);
//            __launch_bounds__(320,3) gives the 68-reg budget to keep all 8
//            LDG.128 in flight (the R8 split kernel at 32 regs serialized
//            them and capped BW at 4.3 TB/s).
// Last block (ticket) finalizes out[2] and resets scratch for graph replay.
// ---------------------------------------------------------------------------

#define MAX_B   8
#define MAX_M   64
#define ABLK    512
#define NTHR    320
#define NWARP   (NTHR / 32)
#define NBLK    444          /* 3 blocks/SM x 148 SMs, single resident wave */

__device__ double g_cls_sum[MAX_B];
__device__ double g_reg_sum[MAX_B];
__device__ int    g_pos_cnt[MAX_B];
__device__ int    g_done;
__device__ int    g_tile_ctr;

__device__ __forceinline__ float lg2f(float x) {
    float r;
    asm("lg2.approx.f32 %0, %1;" : "=f"(r) : "f"(x));
    return r;
}

#define LCL   (-13.28771237954945f)        /* lg2(1e-4) */
#define NEG_W (-0.34657359027997264f)      /* -0.5*ln(2) */

// sum over 4 elements of v^2 * max(lg2(1-v), LCL)
__device__ __forceinline__ float neg4(float4 v) {
    float l0 = fmaxf(lg2f(1.0f - v.x), LCL);
    float l1 = fmaxf(lg2f(1.0f - v.y), LCL);
    float l2 = fmaxf(lg2f(1.0f - v.z), LCL);
    float l3 = fmaxf(lg2f(1.0f - v.w), LCL);
    float s0 = fmaf(v.x * v.x, l0, v.y * v.y * l1);
    float s1 = fmaf(v.z * v.z, l2, v.w * v.w * l3);
    return s0 + s1;
}

__global__ void __launch_bounds__(NTHR, 3)
focal_persistent_kernel(const float* __restrict__ cls,          // [B,A,C]
                        const float* __restrict__ regressions,  // [B,A,4]
                        const float* __restrict__ anchors,      // [A,4]
                        const float* __restrict__ annotations,  // [B,M,5]
                        float* __restrict__ out,
                        int A, int C, int M, int B,
                        int bx, int nTiles, int total_blocks)
{
    const int tid  = threadIdx.x;
    const int lane = tid & 31;
    const int warp = tid >> 5;

    __shared__ float4 s_box[MAX_M];
    __shared__ float  s_area[MAX_M];
    __shared__ float  s_lab[MAX_M];
    __shared__ float  s_w[ABLK];
    __shared__ float  sw_c[NWARP], sw_r[NWARP];
    __shared__ int    sw_i[NWARP];
    __shared__ int    s_t;
    __shared__ int    s_last;

    int curb = -1;    // image whose annotations are staged in smem

    while (true) {
        if (tid == 0) s_t = atomicAdd(&g_tile_ctr, 1);
        __syncthreads();                 // publish s_t; also fences smem reuse
        const int t = s_t;
        if (t >= nTiles) break;
        const int b  = t / bx;
        const int a0 = (t - b * bx) * ABLK;
        const int nA = min(ABLK, A - a0);

        // ---- per-image annotation staging (skipped when unchanged) ----
        if (b != curb) {
            if (tid < M) {
                const float* an = annotations + (size_t)b * M * 5 + tid * 5;
                float x1 = an[0], y1 = an[1], x2 = an[2], y2 = an[3];
                s_box[tid]  = make_float4(x1, y1, x2, y2);
                s_area[tid] = (x2 - x1) * (y2 - y1);
                s_lab[tid]  = an[4];
            }
            curb = b;
            __syncthreads();
        }

        // ================= Phase A: assignment =================
        float fixsum = 0.0f, rsum = 0.0f;
        int   pcnt   = 0;

        for (int la = tid; la < nA; la += NTHR) {
            const int a = a0 + la;
            float4 an = reinterpret_cast<const float4*>(anchors)[a];
            float aw = an.z - an.x;
            float ah = an.w - an.y;
            float area_a = aw * ah;

            float bin, bS;
            int   bi = 0;
            {
                float4 bo = s_box[0];
                float iw = fmaxf(fminf(an.z, bo.z) - fmaxf(an.x, bo.x), 0.0f);
                float ih = fmaxf(fminf(an.w, bo.w) - fmaxf(an.y, bo.y), 0.0f);
                bin = iw * ih;
                bS  = area_a + s_area[0];
            }
            #pragma unroll 8
            for (int m = 1; m < M; m++) {
                float4 bo = s_box[m];
                float iw = fmaxf(fminf(an.z, bo.z) - fmaxf(an.x, bo.x), 0.0f);
                float ih = fmaxf(fminf(an.w, bo.w) - fmaxf(an.y, bo.y), 0.0f);
                float inter = iw * ih;
                float S     = area_a + s_area[m];
                // iou_m > iou_best <=> inter*bS > bin*S (cross terms cancel)
                if (inter * bS > bin * S) { bi = m; bin = inter; bS = S; }
            }

            // iou = bin/(bS-bin): >=0.5 <=> 3*bin>=bS ; >=0.4 <=> 3.5*bin>=bS
            bool pos = (3.0f * bin >= bS);
            bool ign = (!pos) && (3.5f * bin >= bS);
            s_w[la] = ign ? 0.0f : NEG_W;

            if (pos) {
                pcnt++;
                float4 gb = s_box[bi];
                float gw = gb.z - gb.x, gh = gb.w - gb.y;
                float gcx = gb.x + 0.5f * gw, gcy = gb.y + 0.5f * gh;
                gw = fmaxf(gw, 1.0f);
                gh = fmaxf(gh, 1.0f);
                float acx = an.x + 0.5f * aw, acy = an.y + 0.5f * ah;
                float t0 = __fdividef(gcx - acx, aw) * 10.0f;
                float t1 = __fdividef(gcy - acy, ah) * 10.0f;
                float t2 = __logf(__fdividef(gw, aw)) * 5.0f;
                float t3 = __logf(__fdividef(gh, ah)) * 5.0f;

                float4 rg = reinterpret_cast<const float4*>(regressions)[(size_t)b * A + a];
                const float th = 1.0f / 9.0f;
                const float c2 = 0.5f / 9.0f;
                float d;
                d = fabsf(t0 - rg.x); rsum += (d <= th) ? 4.5f * d * d : d - c2;
                d = fabsf(t1 - rg.y); rsum += (d <= th) ? 4.5f * d * d : d - c2;
                d = fabsf(t2 - rg.z); rsum += (d <= th) ? 4.5f * d * d : d - c2;
                d = fabsf(t3 - rg.w); rsum += (d <= th) ? 4.5f * d * d : d - c2;

                // classification fix-up for the true class
                int label = (int)s_lab[bi];
                float v = cls[((size_t)b * A + a) * C + label];
                fixsum -= NEG_W * (v * v * fmaxf(lg2f(1.0f - v), LCL));
                float pp = fminf(fmaxf(v, 1e-4f), 1.0f - 1e-4f);
                float qq = 1.0f - pp;
                fixsum += 0.5f * qq * qq * (-__logf(pp));
            }
        }
        __syncthreads();                 // s_w ready for phase B

        // ================= Phase B: classification stream =================
        float csum = fixsum;
        if (C == 80 && nA == ABLK) {
            const float4* base = reinterpret_cast<const float4*>(
                cls + ((size_t)b * A + a0) * 80);
            // 10240 float4 / 320 threads = 32 steps; 8 loads in flight.
            float acc0 = 0.0f, acc1 = 0.0f, acc2 = 0.0f, acc3 = 0.0f;
            int idx = tid;
            int la  = tid / 20;
            #pragma unroll
            for (int k = 0; k < 4; k++) {
                float4 v0 = __ldcs(base + idx);
                float4 v1 = __ldcs(base + idx + 1 * NTHR);
                float4 v2 = __ldcs(base + idx + 2 * NTHR);
                float4 v3 = __ldcs(base + idx + 3 * NTHR);
                float4 v4 = __ldcs(base + idx + 4 * NTHR);
                float4 v5 = __ldcs(base + idx + 5 * NTHR);
                float4 v6 = __ldcs(base + idx + 6 * NTHR);
                float4 v7 = __ldcs(base + idx + 7 * NTHR);
                acc0 = fmaf(s_w[la      ], neg4(v0), acc0);
                acc1 = fmaf(s_w[la +  16], neg4(v1), acc1);
                acc2 = fmaf(s_w[la +  32], neg4(v2), acc2);
                acc3 = fmaf(s_w[la +  48], neg4(v3), acc3);
                acc0 = fmaf(s_w[la +  64], neg4(v4), acc0);
                acc1 = fmaf(s_w[la +  80], neg4(v5), acc1);
                acc2 = fmaf(s_w[la +  96], neg4(v6), acc2);
                acc3 = fmaf(s_w[la + 112], neg4(v7), acc3);
                idx += 8 * NTHR;
                la  += 128;
            }
            csum += (acc0 + acc1) + (acc2 + acc3);
        } else {
            const float4* base = reinterpret_cast<const float4*>(
                cls + ((size_t)b * A + a0) * C);
            const int n4 = (nA * C) >> 2;
            for (int idx = tid; idx < n4; idx += NTHR) {
                int aa = (idx << 2) / C;
                csum = fmaf(s_w[aa], neg4(__ldcs(base + idx)), csum);
            }
        }

        // ---- per-tile block reduce + atomics ----
        float clssum = csum, regsum = rsum;
        int   poscnt = pcnt;
        #pragma unroll
        for (int off = 16; off > 0; off >>= 1) {
            clssum += __shfl_down_sync(0xFFFFFFFFu, clssum, off);
            regsum += __shfl_down_sync(0xFFFFFFFFu, regsum, off);
            poscnt += __shfl_down_sync(0xFFFFFFFFu, poscnt, off);
        }
        if (lane == 0) { sw_c[warp] = clssum; sw_r[warp] = regsum; sw_i[warp] = poscnt; }
        __syncthreads();
        if (warp == 0) {
            float cs = (lane < NWARP) ? sw_c[lane] : 0.0f;
            float rs = (lane < NWARP) ? sw_r[lane] : 0.0f;
            int   pc = (lane < NWARP) ? sw_i[lane] : 0;
            #pragma unroll
            for (int off = 8; off > 0; off >>= 1) {
                cs += __shfl_down_sync(0xFFFFFFFFu, cs, off);
                rs += __shfl_down_sync(0xFFFFFFFFu, rs, off);
                pc += __shfl_down_sync(0xFFFFFFFFu, pc, off);
            }
            if (lane == 0) {
                atomicAdd(&g_cls_sum[b], (double)cs);
                if (rs != 0.0f) atomicAdd(&g_reg_sum[b], (double)rs);
                if (pc != 0)    atomicAdd(&g_pos_cnt[b], pc);
            }
        }
    }

    // ================= ticket + finalize =================
    if (tid == 0) {
        __threadfence();
        int prev = atomicAdd(&g_done, 1);
        s_last = (prev == total_blocks - 1) ? 1 : 0;
    }
    __syncthreads();

    if (s_last) {
        __threadfence();
        if (warp == 0) {
            double cm = 0.0, rm = 0.0;
            if (lane < B) {
                double cv = *((volatile double*)&g_cls_sum[lane]);
                double rv = *((volatile double*)&g_reg_sum[lane]);
                int    pv = *((volatile int*)&g_pos_cnt[lane]);
                double np = (double)pv;
                cm = cv / fmax(np, 1.0);
                rm = (pv > 0) ? rv / fmax(np * 4.0, 1.0) : 0.0;
            }
            #pragma unroll
            for (int off = 16; off > 0; off >>= 1) {
                cm += __shfl_down_sync(0xFFFFFFFFu, cm, off);
                rm += __shfl_down_sync(0xFFFFFFFFu, rm, off);
            }
            if (lane == 0) {
                out[0] = (float)(cm / (double)B);
                out[1] = (float)(rm / (double)B);
                g_done = 0;
                g_tile_ctr = 0;
            }
            if (lane < B) {
                g_cls_sum[lane] = 0.0;
                g_reg_sum[lane] = 0.0;
                g_pos_cnt[lane] = 0;
            }
        }
    }
}

// ---------------------------------------------------------------------------
extern "C" void kernel_launch(void* const* d_in, const int* in_sizes, int n_in,
                              void* d_out, int out_size)
{
    const float* classifications = (const float*)d_in[0];  // [B,A,C]
    const float* regressions     = (const float*)d_in[1];  // [B,A,4]
    const float* anchors         = (const float*)d_in[2];  // [1,A,4]
    const float* annotations     = (const float*)d_in[3];  // [B,M,5]
    float* out = (float*)d_out;

    const int A = in_sizes[2] / 4;
    const int B = in_sizes[1] / (4 * A);
    const int C = in_sizes[0] / (B * A);
    const int M = in_sizes[3] / (5 * B);

    const int bx     = (A + ABLK - 1) / ABLK;
    const int nTiles = bx * B;

    focal_persistent_kernel<<<NBLK, NTHR>>>(classifications, regressions,
                                            anchors, annotations, out,
                                            A, C, M, B, bx, nTiles, NBLK);
    (void)n_in; (void)out_size;
}